// round 6
// baseline (speedup 1.0000x reference)
#include <cuda_runtime.h>
#include <cuda_fp16.h>

// B=4, C=64, D=16, H=64, W=64, C8=8, k=38 -> thr = sorted_ascending[26] of 64
#define EPSBN 1e-5f
typedef unsigned long long ull;

// ---------------- packed f32x2 helpers (fma pipe) ----------------
__device__ __forceinline__ ull pk(float lo, float hi) {
  ull r; asm("mov.b64 %0,{%1,%2};" : "=l"(r) : "f"(lo), "f"(hi)); return r;
}
__device__ __forceinline__ void upk(float& lo, float& hi, ull v) {
  asm("mov.b64 {%0,%1},%2;" : "=f"(lo), "=f"(hi) : "l"(v));
}
__device__ __forceinline__ ull fma2(ull a, ull b, ull c) {
  ull d; asm("fma.rn.f32x2 %0,%1,%2,%3;" : "=l"(d) : "l"(a), "l"(b), "l"(c)); return d;
}
__device__ __forceinline__ float silu_f(float v) {
  return v * (1.0f / (1.0f + __expf(-v)));
}

// ---------------- params ----------------
struct C2 {
  ull w1o[256];   // [c*4+j] = pk(w1t[c][2j], w1t[c][2j+1]), bn2 scale folded
  ull w2o[256];   // [c*4+j] = pk(w2[c][2j], w2[c][2j+1])
  ull b1o[4];     // pk(b1_eff[2j], b1_eff[2j+1])
  float b2[64];
  float alpha;
};
__device__   C2 g_c2;
__constant__ C2 c2;
__device__ __half g_y1[16777216];   // 32MB; linear indexing matches x

// ---------------- kernel 1: depthwise conv + BN + SiLU -> fp16 y1 ----------
// Conflict-free 4-wide mapping (wq=tid&15) + packed f32x2 accumulation.
#define T1PITCH 72
__global__ void __launch_bounds__(256, 2)
k_dwconv(const float* __restrict__ x,
         const float* __restrict__ wdw,
         const float* __restrict__ g1, const float* __restrict__ be1,
         const float* __restrict__ m1, const float* __restrict__ v1,
         const float* __restrict__ wp1, const float* __restrict__ bp1,
         const float* __restrict__ g2, const float* __restrict__ be2,
         const float* __restrict__ m2, const float* __restrict__ v2,
         const float* __restrict__ wp2, const float* __restrict__ bp2,
         const float* __restrict__ alpha) {
  __shared__ float tile[68 * T1PITCH];
  int p = blockIdx.x;               // ((b*64+c)*16+d)
  int c = (p >> 4) & 63;
  int tid = threadIdx.x;

  // block 0 folds pointwise params alongside its conv work
  if (p == 0) {
    int cc = tid >> 2, j = tid & 3;
    int o0 = 2 * j, o1 = o0 + 1;
    float s2a = __ldg(g2 + o0) * rsqrtf(__ldg(v2 + o0) + EPSBN);
    float s2b = __ldg(g2 + o1) * rsqrtf(__ldg(v2 + o1) + EPSBN);
    g_c2.w1o[cc * 4 + j] = pk(__ldg(wp1 + o0 * 64 + cc) * s2a,
                              __ldg(wp1 + o1 * 64 + cc) * s2b);
    g_c2.w2o[cc * 4 + j] = pk(__ldg(wp2 + cc * 8 + o0), __ldg(wp2 + cc * 8 + o1));
    if (tid < 4) {
      int p0 = 2 * tid, p1 = p0 + 1;
      float sa = __ldg(g2 + p0) * rsqrtf(__ldg(v2 + p0) + EPSBN);
      float sb = __ldg(g2 + p1) * rsqrtf(__ldg(v2 + p1) + EPSBN);
      g_c2.b1o[tid] = pk((__ldg(bp1 + p0) - __ldg(m2 + p0)) * sa + __ldg(be2 + p0),
                         (__ldg(bp1 + p1) - __ldg(m2 + p1)) * sb + __ldg(be2 + p1));
    }
    if (tid < 64) g_c2.b2[tid] = __ldg(bp2 + tid);
    if (tid == 0) g_c2.alpha = __ldg(alpha);
  }

  for (int i = tid; i < 68 * T1PITCH; i += 256) tile[i] = 0.f;
  __syncthreads();
  const float* xp = x + (size_t)p * 4096;
  #pragma unroll
  for (int it = 0; it < 4; it++) {
    int i = tid + it * 256;
    int h = i >> 4, q = i & 15;
    float4 v = *reinterpret_cast<const float4*>(xp + h * 64 + q * 4);
    float* dst = &tile[(h + 2) * T1PITCH + q * 4 + 2];
    dst[0] = v.x; dst[1] = v.y; dst[2] = v.z; dst[3] = v.w;
  }
  __syncthreads();

  float s1 = __ldg(g1 + c) * rsqrtf(__ldg(v1 + c) + EPSBN);
  float t1 = __ldg(be1 + c) - __ldg(m1 + c) * s1;
  ull W[25];
  #pragma unroll
  for (int j = 0; j < 25; j++) {
    float w = __ldg(wdw + c * 25 + j) * s1;
    W[j] = pk(w, w);
  }

  int wq = tid & 15;        // outputs w = 4wq..4wq+3
  int hb = tid >> 4;
  __half2* yp2 = reinterpret_cast<__half2*>(g_y1) + (size_t)p * 2048;

  #pragma unroll
  for (int g = 0; g < 4; g++) {
    int h = hb + g * 16;
    ull A01 = pk(t1, t1), A23 = A01;
    #pragma unroll
    for (int r = 0; r < 5; r++) {
      const float* row = &tile[(h + r) * T1PITCH + 4 * wq];
      float4 va = *reinterpret_cast<const float4*>(row);
      float4 vb = *reinterpret_cast<const float4*>(row + 4);
      ull E0 = pk(va.x, va.y), E1 = pk(va.z, va.w);
      ull E2 = pk(vb.x, vb.y), E3 = pk(vb.z, vb.w);
      ull O0 = pk(va.y, va.z), O1 = pk(va.w, vb.x), O2 = pk(vb.y, vb.z);
      const ull* Wr = &W[r * 5];
      A01 = fma2(Wr[0], E0, A01); A01 = fma2(Wr[1], O0, A01);
      A01 = fma2(Wr[2], E1, A01); A01 = fma2(Wr[3], O1, A01);
      A01 = fma2(Wr[4], E2, A01);
      A23 = fma2(Wr[0], E1, A23); A23 = fma2(Wr[1], O1, A23);
      A23 = fma2(Wr[2], E2, A23); A23 = fma2(Wr[3], O2, A23);
      A23 = fma2(Wr[4], E3, A23);
    }
    float a0, a1, a2, a3; upk(a0, a1, A01); upk(a2, a3, A23);
    __half2 h0 = __floats2half2_rn(silu_f(a0), silu_f(a1));
    __half2 h1 = __floats2half2_rn(silu_f(a2), silu_f(a3));
    uint2 st = make_uint2(*reinterpret_cast<unsigned*>(&h0),
                          *reinterpret_cast<unsigned*>(&h1));
    *reinterpret_cast<uint2*>(yp2 + h * 32 + 2 * wq) = st;
  }
}

// ---------------- kernel 2: lane-pair split pointwise + attn + top-38 -------
// Each location is owned by a lane pair: even lane = channels 0..31,
// odd lane = channels 32..63 (kept NEGATED for the sort). Bitonic merge of
// the two sorted halves is a single shfl.bfly exchange with s[i]=min(s,-r).
__global__ void __launch_bounds__(256, 3)
k_attn(const float* __restrict__ x, float* __restrict__ out) {
  __shared__ float park[256 * 33];          // thread-private 32-val columns
  int tid = threadIdx.x;
  int lane = tid & 31;
  int half = tid & 1;
  int loc = blockIdx.x * 128 + (tid >> 1);  // location 0..262143
  int b = loc >> 16;
  int sp = loc & 65535;
  size_t xb = (size_t)b * 4194304 + (size_t)sp;   // + c*65536
  int cbase = half * 32;

  // pass 1: partial hidden accum over my 32 channels, then pair-reduce
  ull h2[4] = {0, 0, 0, 0};
  #pragma unroll
  for (int i = 0; i < 32; i++) {
    int c = cbase + i;
    float xv = __ldg(x + xb + (size_t)c * 65536);
    ull xx = pk(xv, xv);
    #pragma unroll
    for (int j = 0; j < 4; j++) h2[j] = fma2(c2.w1o[c * 4 + j], xx, h2[j]);
  }
  ull hb2[4];
  #pragma unroll
  for (int j = 0; j < 4; j++) {
    float u, v; upk(u, v, h2[j]);
    u += __shfl_xor_sync(0xffffffffu, u, 1);
    v += __shfl_xor_sync(0xffffffffu, v, 1);
    float bu, bv; upk(bu, bv, c2.b1o[j]);
    hb2[j] = pk(silu_f(u + bu), silu_f(v + bv));
  }

  // pass 2: attn for my 32 channels -> park (raw) + s (negated on odd lane)
  float s[32];
  float* mypark = &park[tid * 33];
  float sgn = half ? -1.0f : 1.0f;
  #pragma unroll
  for (int i = 0; i < 32; i++) {
    int c = cbase + i;
    ull acc = pk(c2.b2[c], 0.0f);
    #pragma unroll
    for (int j = 0; j < 4; j++) acc = fma2(c2.w2o[c * 4 + j], hb2[j], acc);
    float lo, hi; upk(lo, hi, acc);
    float y1v = __half2float(__ldg(g_y1 + xb + (size_t)c * 65536));
    float a = y1v * (lo + hi);
    mypark[i] = a;
    s[i] = a * sgn;
  }

  // full ascending bitonic sort of my 32 values (240 CE)
  #pragma unroll
  for (int k = 2; k <= 32; k <<= 1) {
    #pragma unroll
    for (int j = k >> 1; j > 0; j >>= 1) {
      #pragma unroll
      for (int i = 0; i < 32; i++) {
        int l = i ^ j;
        if (l > i) {
          float a = s[i], bz = s[l];
          float lo = fminf(a, bz), hi = fmaxf(a, bz);
          if ((i & k) == 0) { s[i] = lo; s[l] = hi; }
          else              { s[i] = hi; s[l] = lo; }
        }
      }
    }
  }

  // k=64 merge, j=32: exchange with partner lane. Identity holds for both
  // lanes: new_s[i] = min(s[i], -partner_s[i]).
  #pragma unroll
  for (int i = 0; i < 32; i++) {
    float r = __shfl_xor_sync(0xffffffffu, s[i], 1);
    s[i] = fminf(s[i], -r);
  }
  // remaining merge stages pruned to the dependence cone of index 26 (31 CE)
  #define CEA(i, l) { float a_ = s[i], b_ = s[l]; \
                      s[i] = fminf(a_, b_); s[l] = fmaxf(a_, b_); }
  #pragma unroll
  for (int i = 0; i < 16; i++) CEA(i, i + 16);
  #pragma unroll
  for (int i = 16; i < 24; i++) CEA(i, i + 8);
  #pragma unroll
  for (int i = 24; i < 28; i++) CEA(i, i + 4);
  CEA(24, 26); CEA(25, 27);
  CEA(26, 27);
  // thr lives on the even lane; broadcast to the pair
  float thr = __shfl_sync(0xffffffffu, s[26], lane & ~1);
  float alpha = c2.alpha;

  // pass 3: my 32 channels, parked attn (bit-identical) + write out
  #pragma unroll
  for (int i = 0; i < 32; i++) {
    int c = cbase + i;
    float a  = mypark[i];
    float xv = __ldg(x + xb + (size_t)c * 65536);
    float r  = (a >= thr) ? fmaf(alpha, a, xv) : xv;
    out[xb + (size_t)c * 65536] = r;
  }
}

// ---------------------------------------------------------------------------
extern "C" void kernel_launch(void* const* d_in, const int* in_sizes, int n_in,
                              void* d_out, int out_size) {
  const float* x    = (const float*)d_in[0];
  const float* wdw  = (const float*)d_in[1];
  const float* g1   = (const float*)d_in[2];
  const float* be1  = (const float*)d_in[3];
  const float* m1   = (const float*)d_in[4];
  const float* v1   = (const float*)d_in[5];
  const float* wp1  = (const float*)d_in[6];
  const float* bp1  = (const float*)d_in[7];
  const float* g2   = (const float*)d_in[8];
  const float* be2  = (const float*)d_in[9];
  const float* m2   = (const float*)d_in[10];
  const float* v2   = (const float*)d_in[11];
  const float* wp2  = (const float*)d_in[12];
  const float* bp2  = (const float*)d_in[13];
  const float* alpha= (const float*)d_in[14];
  float* out = (float*)d_out;

  k_dwconv<<<4096, 256>>>(x, wdw, g1, be1, m1, v1, wp1, bp1,
                          g2, be2, m2, v2, wp2, bp2, alpha);

  void* gaddr = nullptr;
  cudaGetSymbolAddress(&gaddr, g_c2);
  cudaMemcpyToSymbolAsync(c2, gaddr, sizeof(C2), 0,
                          cudaMemcpyDeviceToDevice, 0);

  k_attn<<<2048, 256>>>(x, out);
}

// round 7
// speedup vs baseline: 1.3756x; 1.3756x over previous
#include <cuda_runtime.h>
#include <cuda_fp16.h>

// B=4, C=64, D=16, H=64, W=64, C8=8, k=38 -> thr = sorted_ascending[26] of 64
#define EPSBN 1e-5f
typedef unsigned long long ull;

// ---------------- packed f32x2 helpers (fma pipe) ----------------
__device__ __forceinline__ ull pk(float lo, float hi) {
  ull r; asm("mov.b64 %0,{%1,%2};" : "=l"(r) : "f"(lo), "f"(hi)); return r;
}
__device__ __forceinline__ void upk(float& lo, float& hi, ull v) {
  asm("mov.b64 {%0,%1},%2;" : "=f"(lo), "=f"(hi) : "l"(v));
}
__device__ __forceinline__ ull fma2(ull a, ull b, ull c) {
  ull d; asm("fma.rn.f32x2 %0,%1,%2,%3;" : "=l"(d) : "l"(a), "l"(b), "l"(c)); return d;
}
__device__ __forceinline__ float silu_f(float v) {
  return v * (1.0f / (1.0f + __expf(-v)));
}

// ---------------- params ----------------
struct C2 {
  ull w1o[256];   // [c*4+j] = pk(w1t[c][2j], w1t[c][2j+1]), bn2 scale folded
  ull w2o[256];   // [c*4+j] = pk(w2[c][2j], w2[c][2j+1])
  ull b1o[4];     // pk(b1_eff[2j], b1_eff[2j+1])
  float b2[64];
  float alpha;
};
__device__   C2 g_c2;
__constant__ C2 c2;
__device__ __half g_y1[16777216];   // 32MB; linear indexing matches x

// ---------------- kernel 1: depthwise conv + BN + SiLU -> fp16 y1 ----------
// R5-proven scalar version: conflict-free wq=tid&15 mapping, ~55 regs,
// 4 CTAs/SM. Block 0 folds pointwise params alongside its conv work.
#define T1PITCH 72
__global__ void __launch_bounds__(256)
k_dwconv(const float* __restrict__ x,
         const float* __restrict__ wdw,
         const float* __restrict__ g1, const float* __restrict__ be1,
         const float* __restrict__ m1, const float* __restrict__ v1,
         const float* __restrict__ wp1, const float* __restrict__ bp1,
         const float* __restrict__ g2, const float* __restrict__ be2,
         const float* __restrict__ m2, const float* __restrict__ v2,
         const float* __restrict__ wp2, const float* __restrict__ bp2,
         const float* __restrict__ alpha) {
  __shared__ float tile[68 * T1PITCH];
  int p = blockIdx.x;               // ((b*64+c)*16+d)
  int c = (p >> 4) & 63;
  int tid = threadIdx.x;

  if (p == 0) {
    int cc = tid >> 2, j = tid & 3;
    int o0 = 2 * j, o1 = o0 + 1;
    float s2a = __ldg(g2 + o0) * rsqrtf(__ldg(v2 + o0) + EPSBN);
    float s2b = __ldg(g2 + o1) * rsqrtf(__ldg(v2 + o1) + EPSBN);
    g_c2.w1o[cc * 4 + j] = pk(__ldg(wp1 + o0 * 64 + cc) * s2a,
                              __ldg(wp1 + o1 * 64 + cc) * s2b);
    g_c2.w2o[cc * 4 + j] = pk(__ldg(wp2 + cc * 8 + o0), __ldg(wp2 + cc * 8 + o1));
    if (tid < 4) {
      int p0 = 2 * tid, p1 = p0 + 1;
      float sa = __ldg(g2 + p0) * rsqrtf(__ldg(v2 + p0) + EPSBN);
      float sb = __ldg(g2 + p1) * rsqrtf(__ldg(v2 + p1) + EPSBN);
      g_c2.b1o[tid] = pk((__ldg(bp1 + p0) - __ldg(m2 + p0)) * sa + __ldg(be2 + p0),
                         (__ldg(bp1 + p1) - __ldg(m2 + p1)) * sb + __ldg(be2 + p1));
    }
    if (tid < 64) g_c2.b2[tid] = __ldg(bp2 + tid);
    if (tid == 0) g_c2.alpha = __ldg(alpha);
  }

  for (int i = tid; i < 68 * T1PITCH; i += 256) tile[i] = 0.f;
  __syncthreads();
  const float* xp = x + (size_t)p * 4096;
  #pragma unroll
  for (int it = 0; it < 4; it++) {
    int i = tid + it * 256;
    int h = i >> 4, q = i & 15;
    float4 v = *reinterpret_cast<const float4*>(xp + h * 64 + q * 4);
    float* dst = &tile[(h + 2) * T1PITCH + q * 4 + 2];
    dst[0] = v.x; dst[1] = v.y; dst[2] = v.z; dst[3] = v.w;
  }
  __syncthreads();

  float s1 = __ldg(g1 + c) * rsqrtf(__ldg(v1 + c) + EPSBN);
  float t1 = __ldg(be1 + c) - __ldg(m1 + c) * s1;
  float wk[25];
  #pragma unroll
  for (int j = 0; j < 25; j++) wk[j] = __ldg(wdw + c * 25 + j) * s1;

  int wq = tid & 15;        // outputs w = 4wq..4wq+3
  int hb = tid >> 4;
  __half2* yp2 = reinterpret_cast<__half2*>(g_y1) + (size_t)p * 2048;

  #pragma unroll
  for (int g = 0; g < 4; g++) {
    int h = hb + g * 16;
    float a0 = t1, a1 = t1, a2 = t1, a3 = t1;
    #pragma unroll
    for (int r = 0; r < 5; r++) {
      const float* row = &tile[(h + r) * T1PITCH + 4 * wq];
      float4 va = *reinterpret_cast<const float4*>(row);
      float4 vb = *reinterpret_cast<const float4*>(row + 4);
      const float* wr = &wk[r * 5];
      a0 = fmaf(wr[0], va.x, fmaf(wr[1], va.y, fmaf(wr[2], va.z, fmaf(wr[3], va.w, fmaf(wr[4], vb.x, a0)))));
      a1 = fmaf(wr[0], va.y, fmaf(wr[1], va.z, fmaf(wr[2], va.w, fmaf(wr[3], vb.x, fmaf(wr[4], vb.y, a1)))));
      a2 = fmaf(wr[0], va.z, fmaf(wr[1], va.w, fmaf(wr[2], vb.x, fmaf(wr[3], vb.y, fmaf(wr[4], vb.z, a2)))));
      a3 = fmaf(wr[0], va.w, fmaf(wr[1], vb.x, fmaf(wr[2], vb.y, fmaf(wr[3], vb.z, fmaf(wr[4], vb.w, a3)))));
    }
    __half2 h0 = __floats2half2_rn(silu_f(a0), silu_f(a1));
    __half2 h1 = __floats2half2_rn(silu_f(a2), silu_f(a3));
    uint2 st = make_uint2(*reinterpret_cast<unsigned*>(&h0),
                          *reinterpret_cast<unsigned*>(&h1));
    *reinterpret_cast<uint2*>(yp2 + h * 32 + 2 * wq) = st;
  }
}

// ---------------- kernel 2: pointwise + attn + top-38 + output ------------
// R5 structure + y1 smem prefetch: y1 LDGs issue in pass 1 (latency hidden
// by the matvec fma chain), pass 2 reads y1 via 29-cyc LDS.
#define CEA(i, l) { float a_ = s[i], b_ = s[l]; \
                    s[i] = fminf(a_, b_); s[l] = fmaxf(a_, b_); }

__global__ void __launch_bounds__(256, 2)
k_attn(const float* __restrict__ x, float* __restrict__ out) {
  extern __shared__ char smem[];
  __half* y1p = reinterpret_cast<__half*>(smem);          // 64*256*2B = 32KB
  float* park = reinterpret_cast<float*>(smem + 32768);   // 64*256*4B = 64KB
  int tid = threadIdx.x;
  int t = blockIdx.x * 256 + tid;
  int b = t >> 16;
  int sp = t & 65535;
  size_t xb = (size_t)b * 4194304 + (size_t)sp;   // + c*65536

  // pass 1: hidden pre-activations; prefetch y1 -> smem along the way
  ull h2[4] = {c2.b1o[0], c2.b1o[1], c2.b1o[2], c2.b1o[3]};
  #pragma unroll
  for (int c = 0; c < 64; c++) {
    float xv = __ldg(x + xb + (size_t)c * 65536);
    __half yv = __ldg(g_y1 + xb + (size_t)c * 65536);
    y1p[c * 256 + tid] = yv;
    ull xx = pk(xv, xv);
    #pragma unroll
    for (int j = 0; j < 4; j++) h2[j] = fma2(c2.w1o[c * 4 + j], xx, h2[j]);
  }
  ull hb2[4];
  #pragma unroll
  for (int j = 0; j < 4; j++) {
    float u, v; upk(u, v, h2[j]);
    hb2[j] = pk(silu_f(u), silu_f(v));
  }

  // pass 2: attn values from smem y1 -> regs (sort) + smem park (output)
  float s[64];
  #pragma unroll
  for (int c = 0; c < 64; c++) {
    ull acc = pk(c2.b2[c], 0.0f);
    #pragma unroll
    for (int j = 0; j < 4; j++) acc = fma2(c2.w2o[c * 4 + j], hb2[j], acc);
    float lo, hi; upk(lo, hi, acc);
    float y1v = __half2float(y1p[c * 256 + tid]);
    float a = y1v * (lo + hi);
    park[c * 256 + tid] = a;
    s[c] = a;
  }

  // bitonic stages k=2..32 (full; 480 CE)
  #pragma unroll
  for (int k = 2; k <= 32; k <<= 1) {
    #pragma unroll
    for (int j = k >> 1; j > 0; j >>= 1) {
      #pragma unroll
      for (int i = 0; i < 64; i++) {
        int l = i ^ j;
        if (l > i) {
          float a = s[i], bz = s[l];
          float lo = fminf(a, bz), hi = fmaxf(a, bz);
          if ((i & k) == 0) { s[i] = lo; s[l] = hi; }
          else              { s[i] = hi; s[l] = lo; }
        }
      }
    }
  }
  // final k=64 merge pruned to dependence cone of index 26 (63 CE)
  #pragma unroll
  for (int i = 0; i < 32; i++) CEA(i, i + 32);
  #pragma unroll
  for (int i = 0; i < 16; i++) CEA(i, i + 16);
  #pragma unroll
  for (int i = 16; i < 24; i++) CEA(i, i + 8);
  #pragma unroll
  for (int i = 24; i < 28; i++) CEA(i, i + 4);
  CEA(24, 26); CEA(25, 27);
  CEA(26, 27);
  float thr = s[26];
  float alpha = c2.alpha;

  // pass 3: parked attn (bit-identical) + write out
  #pragma unroll
  for (int c = 0; c < 64; c++) {
    float a  = park[c * 256 + tid];
    float xv = __ldg(x + xb + (size_t)c * 65536);
    float r  = (a >= thr) ? fmaf(alpha, a, xv) : xv;
    out[xb + (size_t)c * 65536] = r;
  }
}

// ---------------------------------------------------------------------------
extern "C" void kernel_launch(void* const* d_in, const int* in_sizes, int n_in,
                              void* d_out, int out_size) {
  const float* x    = (const float*)d_in[0];
  const float* wdw  = (const float*)d_in[1];
  const float* g1   = (const float*)d_in[2];
  const float* be1  = (const float*)d_in[3];
  const float* m1   = (const float*)d_in[4];
  const float* v1   = (const float*)d_in[5];
  const float* wp1  = (const float*)d_in[6];
  const float* bp1  = (const float*)d_in[7];
  const float* g2   = (const float*)d_in[8];
  const float* be2  = (const float*)d_in[9];
  const float* m2   = (const float*)d_in[10];
  const float* v2   = (const float*)d_in[11];
  const float* wp2  = (const float*)d_in[12];
  const float* bp2  = (const float*)d_in[13];
  const float* alpha= (const float*)d_in[14];
  float* out = (float*)d_out;

  k_dwconv<<<4096, 256>>>(x, wdw, g1, be1, m1, v1, wp1, bp1,
                          g2, be2, m2, v2, wp2, bp2, alpha);

  void* gaddr = nullptr;
  cudaGetSymbolAddress(&gaddr, g_c2);
  cudaMemcpyToSymbolAsync(c2, gaddr, sizeof(C2), 0,
                          cudaMemcpyDeviceToDevice, 0);

  cudaFuncSetAttribute(k_attn, cudaFuncAttributeMaxDynamicSharedMemorySize,
                       98304);
  k_attn<<<1024, 256, 98304>>>(x, out);
}

// round 8
// speedup vs baseline: 1.4542x; 1.0571x over previous
#include <cuda_runtime.h>
#include <cuda_fp16.h>

// B=4, C=64, D=16, H=64, W=64, C8=8, k=38 -> thr = rank-26 ascending of 64
#define EPSBN 1e-5f
typedef unsigned long long ull;

// ---------------- packed f32x2 helpers (fma pipe) ----------------
__device__ __forceinline__ ull pk(float lo, float hi) {
  ull r; asm("mov.b64 %0,{%1,%2};" : "=l"(r) : "f"(lo), "f"(hi)); return r;
}
__device__ __forceinline__ void upk(float& lo, float& hi, ull v) {
  asm("mov.b64 {%0,%1},%2;" : "=f"(lo), "=f"(hi) : "l"(v));
}
__device__ __forceinline__ ull fma2(ull a, ull b, ull c) {
  ull d; asm("fma.rn.f32x2 %0,%1,%2,%3;" : "=l"(d) : "l"(a), "l"(b), "l"(c)); return d;
}
__device__ __forceinline__ float silu_f(float v) {
  return v * (1.0f / (1.0f + __expf(-v)));
}

// ---------------- params ----------------
struct C2 {
  ull w1o[256];   // [c*4+j] = pk(w1t[c][2j], w1t[c][2j+1]), bn2 scale folded
  ull w2o[256];   // [c*4+j] = pk(w2[c][2j], w2[c][2j+1])
  ull b1o[4];     // pk(b1_eff[2j], b1_eff[2j+1])
  float b2[64];
  float alpha;
};
__device__   C2 g_c2;
__constant__ C2 c2;
__device__ __half g_y1[16777216];   // 32MB; linear indexing matches x

// ---------------- kernel 1: depthwise conv + BN + SiLU -> fp16 y1 ----------
// Conflict-free wq=tid&15 LDS.128 pattern; f32x2 accumulation with the packed
// weights held in SMEM (LDS.64 broadcast) so regs stay ~60 (4 CTAs/SM).
#define T1PITCH 72
__global__ void __launch_bounds__(256)
k_dwconv(const float* __restrict__ x,
         const float* __restrict__ wdw,
         const float* __restrict__ g1, const float* __restrict__ be1,
         const float* __restrict__ m1, const float* __restrict__ v1,
         const float* __restrict__ wp1, const float* __restrict__ bp1,
         const float* __restrict__ g2, const float* __restrict__ be2,
         const float* __restrict__ m2, const float* __restrict__ v2,
         const float* __restrict__ wp2, const float* __restrict__ bp2,
         const float* __restrict__ alpha) {
  __shared__ float tile[68 * T1PITCH];
  __shared__ ull Wsm[25];
  int p = blockIdx.x;               // ((b*64+c)*16+d)
  int c = (p >> 4) & 63;
  int tid = threadIdx.x;

  // block 0 folds pointwise params alongside its conv work
  if (p == 0) {
    int cc = tid >> 2, j = tid & 3;
    int o0 = 2 * j, o1 = o0 + 1;
    float s2a = __ldg(g2 + o0) * rsqrtf(__ldg(v2 + o0) + EPSBN);
    float s2b = __ldg(g2 + o1) * rsqrtf(__ldg(v2 + o1) + EPSBN);
    g_c2.w1o[cc * 4 + j] = pk(__ldg(wp1 + o0 * 64 + cc) * s2a,
                              __ldg(wp1 + o1 * 64 + cc) * s2b);
    g_c2.w2o[cc * 4 + j] = pk(__ldg(wp2 + cc * 8 + o0), __ldg(wp2 + cc * 8 + o1));
    if (tid < 4) {
      int p0 = 2 * tid, p1 = p0 + 1;
      float sa = __ldg(g2 + p0) * rsqrtf(__ldg(v2 + p0) + EPSBN);
      float sb = __ldg(g2 + p1) * rsqrtf(__ldg(v2 + p1) + EPSBN);
      g_c2.b1o[tid] = pk((__ldg(bp1 + p0) - __ldg(m2 + p0)) * sa + __ldg(be2 + p0),
                         (__ldg(bp1 + p1) - __ldg(m2 + p1)) * sb + __ldg(be2 + p1));
    }
    if (tid < 64) g_c2.b2[tid] = __ldg(bp2 + tid);
    if (tid == 0) g_c2.alpha = __ldg(alpha);
  }

  // packed folded weights -> smem (threads 0..24)
  if (tid < 25) {
    float s1 = __ldg(g1 + c) * rsqrtf(__ldg(v1 + c) + EPSBN);
    float w = __ldg(wdw + c * 25 + tid) * s1;
    Wsm[tid] = pk(w, w);
  }

  for (int i = tid; i < 68 * T1PITCH; i += 256) tile[i] = 0.f;
  __syncthreads();
  const float* xp = x + (size_t)p * 4096;
  #pragma unroll
  for (int it = 0; it < 4; it++) {
    int i = tid + it * 256;
    int h = i >> 4, q = i & 15;
    float4 v = *reinterpret_cast<const float4*>(xp + h * 64 + q * 4);
    float* dst = &tile[(h + 2) * T1PITCH + q * 4 + 2];
    dst[0] = v.x; dst[1] = v.y; dst[2] = v.z; dst[3] = v.w;
  }
  __syncthreads();

  float s1 = __ldg(g1 + c) * rsqrtf(__ldg(v1 + c) + EPSBN);
  float t1 = __ldg(be1 + c) - __ldg(m1 + c) * s1;

  int wq = tid & 15;        // outputs w = 4wq..4wq+3
  int hb = tid >> 4;        // base row; groups at hb, hb+16, hb+32, hb+48

  ull A[8];                 // A[2g] = outputs (w0,w1), A[2g+1] = (w2,w3)
  #pragma unroll
  for (int m = 0; m < 8; m++) A[m] = pk(t1, t1);

  #pragma unroll
  for (int r = 0; r < 5; r++) {
    ull w0 = Wsm[r * 5 + 0], w1 = Wsm[r * 5 + 1], w2 = Wsm[r * 5 + 2],
        w3 = Wsm[r * 5 + 3], w4 = Wsm[r * 5 + 4];
    #pragma unroll
    for (int g = 0; g < 4; g++) {
      const float* row = &tile[(hb + 16 * g + r) * T1PITCH + 4 * wq];
      float4 va = *reinterpret_cast<const float4*>(row);
      float4 vb = *reinterpret_cast<const float4*>(row + 4);
      ull E01 = pk(va.x, va.y), E23 = pk(va.z, va.w);
      ull E45 = pk(vb.x, vb.y), E67 = pk(vb.z, vb.w);
      ull O12 = pk(va.y, va.z), O34 = pk(va.w, vb.x), O56 = pk(vb.y, vb.z);
      ull a0 = A[2 * g], a1 = A[2 * g + 1];
      a0 = fma2(w0, E01, a0); a0 = fma2(w1, O12, a0);
      a0 = fma2(w2, E23, a0); a0 = fma2(w3, O34, a0);
      a0 = fma2(w4, E45, a0);
      a1 = fma2(w0, E23, a1); a1 = fma2(w1, O34, a1);
      a1 = fma2(w2, E45, a1); a1 = fma2(w3, O56, a1);
      a1 = fma2(w4, E67, a1);
      A[2 * g] = a0; A[2 * g + 1] = a1;
    }
  }

  __half2* yp2 = reinterpret_cast<__half2*>(g_y1) + (size_t)p * 2048;
  #pragma unroll
  for (int g = 0; g < 4; g++) {
    int h = hb + 16 * g;
    float a0, a1, a2, a3;
    upk(a0, a1, A[2 * g]); upk(a2, a3, A[2 * g + 1]);
    __half2 h0 = __floats2half2_rn(silu_f(a0), silu_f(a1));
    __half2 h1 = __floats2half2_rn(silu_f(a2), silu_f(a3));
    uint2 st = make_uint2(*reinterpret_cast<unsigned*>(&h0),
                          *reinterpret_cast<unsigned*>(&h1));
    *reinterpret_cast<uint2*>(yp2 + h * 32 + 2 * wq) = st;
  }
}

// ---------------- kernel 2: pointwise + attn + top-38 + output ------------
// fp16-packed bitonic sort: lane-lo = channels 0..31 ascending,
// lane-hi = channels 32..63 NEGATED (so ascending in negated space =
// descending real) -> one 240-CE network sorts both halves; k=64 merge
// first stage is min(ph, -swap(ph)); remaining cone to rank 26 = 31 ops.
__global__ void __launch_bounds__(256, 3)
k_attn(const float* __restrict__ x, float* __restrict__ out) {
  extern __shared__ float park[];           // 64*256 floats = 64KB
  int tid = threadIdx.x;
  int t = blockIdx.x * 256 + tid;
  int b = t >> 16;
  int sp = t & 65535;
  size_t xb = (size_t)b * 4194304 + (size_t)sp;   // + c*65536

  // pass 1: 8 hidden pre-activations (packed over o-pairs)
  ull h2[4] = {c2.b1o[0], c2.b1o[1], c2.b1o[2], c2.b1o[3]};
  #pragma unroll
  for (int c = 0; c < 64; c++) {
    float xv = __ldg(x + xb + (size_t)c * 65536);
    ull xx = pk(xv, xv);
    #pragma unroll
    for (int j = 0; j < 4; j++) h2[j] = fma2(c2.w1o[c * 4 + j], xx, h2[j]);
  }
  ull hb2[4];
  #pragma unroll
  for (int j = 0; j < 4; j++) {
    float u, v; upk(u, v, h2[j]);
    hb2[j] = pk(silu_f(u), silu_f(v));
  }

  // pass 2: attn for c and c+32 together -> park fp32 + packed fp16 keys
  __half2 ph[32];
  float* mypark = park + tid;
  #pragma unroll
  for (int i = 0; i < 32; i++) {
    ull accA = pk(c2.b2[i], 0.0f);
    ull accB = pk(c2.b2[i + 32], 0.0f);
    #pragma unroll
    for (int j = 0; j < 4; j++) {
      accA = fma2(c2.w2o[i * 4 + j], hb2[j], accA);
      accB = fma2(c2.w2o[(i + 32) * 4 + j], hb2[j], accB);
    }
    float loA, hiA, loB, hiB;
    upk(loA, hiA, accA); upk(loB, hiB, accB);
    float y1A = __half2float(__ldg(g_y1 + xb + (size_t)i * 65536));
    float y1B = __half2float(__ldg(g_y1 + xb + (size_t)(i + 32) * 65536));
    float aA = y1A * (loA + hiA);
    float aB = y1B * (loB + hiB);
    mypark[i * 256] = aA;
    mypark[(i + 32) * 256] = aB;
    ph[i] = __floats2half2_rn(aA, -aB);
  }

  // packed bitonic sort-32 (both lanes ascending; 240 CE)
  #pragma unroll
  for (int k = 2; k <= 32; k <<= 1) {
    #pragma unroll
    for (int j = k >> 1; j > 0; j >>= 1) {
      #pragma unroll
      for (int i = 0; i < 32; i++) {
        int l = i ^ j;
        if (l > i) {
          __half2 a = ph[i], bz = ph[l];
          __half2 mn = __hmin2(a, bz), mx = __hmax2(a, bz);
          if ((i & k) == 0) { ph[i] = mn; ph[l] = mx; }
          else              { ph[i] = mx; ph[l] = mn; }
        }
      }
    }
  }

  // k=64 merge stage j=32: lower half (32 smallest) = min(lo_i, -hi_i)
  __half hv[32];
  #pragma unroll
  for (int i = 0; i < 32; i++) {
    __half2 sw = __lowhigh2highlow(ph[i]);
    __half2 m = __hmin2(ph[i], __hneg2(sw));
    hv[i] = __low2half(m);
  }
  // pruned cone to index 26: keep only surviving halves (31 ops)
  #pragma unroll
  for (int i = 0; i < 16; i++) hv[i + 16] = __hmax(hv[i], hv[i + 16]);
  #pragma unroll
  for (int i = 16; i < 24; i++) hv[i + 8] = __hmax(hv[i], hv[i + 8]);
  #pragma unroll
  for (int i = 24; i < 28; i++) hv[i] = __hmin(hv[i], hv[i + 4]);
  hv[26] = __hmax(hv[24], hv[26]);
  hv[27] = __hmax(hv[25], hv[27]);
  float thr = __half2float(__hmin(hv[26], hv[27]));
  float alpha = c2.alpha;

  // pass 3: parked attn + write out
  #pragma unroll
  for (int c = 0; c < 64; c++) {
    float a  = mypark[c * 256];
    float xv = __ldg(x + xb + (size_t)c * 65536);
    float r  = (a >= thr) ? fmaf(alpha, a, xv) : xv;
    out[xb + (size_t)c * 65536] = r;
  }
}

// ---------------------------------------------------------------------------
extern "C" void kernel_launch(void* const* d_in, const int* in_sizes, int n_in,
                              void* d_out, int out_size) {
  const float* x    = (const float*)d_in[0];
  const float* wdw  = (const float*)d_in[1];
  const float* g1   = (const float*)d_in[2];
  const float* be1  = (const float*)d_in[3];
  const float* m1   = (const float*)d_in[4];
  const float* v1   = (const float*)d_in[5];
  const float* wp1  = (const float*)d_in[6];
  const float* bp1  = (const float*)d_in[7];
  const float* g2   = (const float*)d_in[8];
  const float* be2  = (const float*)d_in[9];
  const float* m2   = (const float*)d_in[10];
  const float* v2   = (const float*)d_in[11];
  const float* wp2  = (const float*)d_in[12];
  const float* bp2  = (const float*)d_in[13];
  const float* alpha= (const float*)d_in[14];
  float* out = (float*)d_out;

  k_dwconv<<<4096, 256>>>(x, wdw, g1, be1, m1, v1, wp1, bp1,
                          g2, be2, m2, v2, wp2, bp2, alpha);

  void* gaddr = nullptr;
  cudaGetSymbolAddress(&gaddr, g_c2);
  cudaMemcpyToSymbolAsync(c2, gaddr, sizeof(C2), 0,
                          cudaMemcpyDeviceToDevice, 0);

  cudaFuncSetAttribute(k_attn, cudaFuncAttributeMaxDynamicSharedMemorySize,
                       65536);
  k_attn<<<1024, 256, 65536>>>(x, out);
}

// round 9
// speedup vs baseline: 1.5476x; 1.0642x over previous
#include <cuda_runtime.h>
#include <cuda_fp16.h>

// B=4, C=64, D=16, H=64, W=64, C8=8, k=38 -> thr = rank-26 ascending of 64
#define EPSBN 1e-5f
typedef unsigned long long ull;

// ---------------- packed f32x2 helpers (fma pipe) ----------------
__device__ __forceinline__ ull pk(float lo, float hi) {
  ull r; asm("mov.b64 %0,{%1,%2};" : "=l"(r) : "f"(lo), "f"(hi)); return r;
}
__device__ __forceinline__ void upk(float& lo, float& hi, ull v) {
  asm("mov.b64 {%0,%1},%2;" : "=f"(lo), "=f"(hi) : "l"(v));
}
__device__ __forceinline__ ull fma2(ull a, ull b, ull c) {
  ull d; asm("fma.rn.f32x2 %0,%1,%2,%3;" : "=l"(d) : "l"(a), "l"(b), "l"(c)); return d;
}
__device__ __forceinline__ float silu_f(float v) {
  return v * (1.0f / (1.0f + __expf(-v)));
}

// ---------------- params ----------------
struct C2 {
  ull w1o[256];   // [c*4+j] = pk(w1t[c][2j], w1t[c][2j+1]), bn2 scale folded
  ull w2o[256];   // [c*4+j] = pk(w2[c][2j], w2[c][2j+1])
  ull b1o[4];     // pk(b1_eff[2j], b1_eff[2j+1])
  float b2[64];
  float alpha;
};
__device__   C2 g_c2;
__constant__ C2 c2;
__device__ __half g_y1[16777216];   // 32MB; linear indexing matches x

// ---------------- kernel 1: depthwise conv + BN + SiLU -> fp16 y1 ----------
// 8-wide output tiles: 3 aligned LDS.128 cover exactly the 12 floats/row.
// Lane remap (phase = 4 wq x 2 rows) + pitch 76 (=12 words mod 32) makes all
// LDS.128 conflict-free. f32x2 accumulation: 6 even pairs alias the quads
// free; 5 odd pairs packed once per row, shared across the 4 output pairs.
#define PITCH 76
__global__ void __launch_bounds__(256)
k_dwconv(const float* __restrict__ x,
         const float* __restrict__ wdw,
         const float* __restrict__ g1, const float* __restrict__ be1,
         const float* __restrict__ m1, const float* __restrict__ v1,
         const float* __restrict__ wp1, const float* __restrict__ bp1,
         const float* __restrict__ g2, const float* __restrict__ be2,
         const float* __restrict__ m2, const float* __restrict__ v2,
         const float* __restrict__ wp2, const float* __restrict__ bp2,
         const float* __restrict__ alpha) {
  __shared__ float tile[68 * PITCH];
  __shared__ ull Wsm[25];
  int p = blockIdx.x;               // ((b*64+c)*16+d)
  int c = (p >> 4) & 63;
  int tid = threadIdx.x;

  // block 0 folds pointwise params alongside its conv work
  if (p == 0) {
    int cc = tid >> 2, j = tid & 3;
    int o0 = 2 * j, o1 = o0 + 1;
    float s2a = __ldg(g2 + o0) * rsqrtf(__ldg(v2 + o0) + EPSBN);
    float s2b = __ldg(g2 + o1) * rsqrtf(__ldg(v2 + o1) + EPSBN);
    g_c2.w1o[cc * 4 + j] = pk(__ldg(wp1 + o0 * 64 + cc) * s2a,
                              __ldg(wp1 + o1 * 64 + cc) * s2b);
    g_c2.w2o[cc * 4 + j] = pk(__ldg(wp2 + cc * 8 + o0), __ldg(wp2 + cc * 8 + o1));
    if (tid < 4) {
      int p0 = 2 * tid, p1 = p0 + 1;
      float sa = __ldg(g2 + p0) * rsqrtf(__ldg(v2 + p0) + EPSBN);
      float sb = __ldg(g2 + p1) * rsqrtf(__ldg(v2 + p1) + EPSBN);
      g_c2.b1o[tid] = pk((__ldg(bp1 + p0) - __ldg(m2 + p0)) * sa + __ldg(be2 + p0),
                         (__ldg(bp1 + p1) - __ldg(m2 + p1)) * sb + __ldg(be2 + p1));
    }
    if (tid < 64) g_c2.b2[tid] = __ldg(bp2 + tid);
    if (tid == 0) g_c2.alpha = __ldg(alpha);
  }

  // packed folded depthwise weights -> smem
  if (tid < 25) {
    float s1 = __ldg(g1 + c) * rsqrtf(__ldg(v1 + c) + EPSBN);
    float w = __ldg(wdw + c * 25 + tid) * s1;
    Wsm[tid] = pk(w, w);
  }

  for (int i = tid; i < 68 * PITCH; i += 256) tile[i] = 0.f;
  __syncthreads();
  const float* xp = x + (size_t)p * 4096;
  #pragma unroll
  for (int it = 0; it < 4; it++) {
    int i = tid + it * 256;
    int h = i >> 4, q = i & 15;
    float4 v = *reinterpret_cast<const float4*>(xp + h * 64 + q * 4);
    float* dst = &tile[(h + 2) * PITCH + q * 4 + 2];
    dst[0] = v.x; dst[1] = v.y; dst[2] = v.z; dst[3] = v.w;
  }
  __syncthreads();

  float t1;
  {
    float s1 = __ldg(g1 + c) * rsqrtf(__ldg(v1 + c) + EPSBN);
    t1 = __ldg(be1 + c) - __ldg(m1 + c) * s1;
  }

  // lane remap: wq from tid bits {0,1,3}; hb from bits {2,4..7}
  int wq = (tid & 3) | ((tid >> 1) & 4);          // 0..7, outputs w=8wq..8wq+7
  int hb = ((tid >> 2) & 1) | ((tid >> 3) & 0x1E); // 0..31; rows hb, hb+32

  ull A[8];                 // [4g+m]: group g row, output pair m
  #pragma unroll
  for (int m = 0; m < 8; m++) A[m] = pk(t1, t1);

  #pragma unroll
  for (int r = 0; r < 5; r++) {
    ull W0 = Wsm[5*r+0], W1 = Wsm[5*r+1], W2 = Wsm[5*r+2],
        W3 = Wsm[5*r+3], W4 = Wsm[5*r+4];
    #pragma unroll
    for (int g = 0; g < 2; g++) {
      const float* row = &tile[(hb + 32 * g + r) * PITCH + 8 * wq];
      float4 Q0 = *reinterpret_cast<const float4*>(row);
      float4 Q1 = *reinterpret_cast<const float4*>(row + 4);
      float4 Q2 = *reinterpret_cast<const float4*>(row + 8);
      ull E0 = pk(Q0.x, Q0.y), E1 = pk(Q0.z, Q0.w), E2 = pk(Q1.x, Q1.y),
          E3 = pk(Q1.z, Q1.w), E4 = pk(Q2.x, Q2.y), E5 = pk(Q2.z, Q2.w);
      ull O0 = pk(Q0.y, Q0.z), O1 = pk(Q0.w, Q1.x), O2 = pk(Q1.y, Q1.z),
          O3 = pk(Q1.w, Q2.x), O4 = pk(Q2.y, Q2.z);
      ull E[6] = {E0, E1, E2, E3, E4, E5};
      ull O[5] = {O0, O1, O2, O3, O4};
      #pragma unroll
      for (int m = 0; m < 4; m++) {
        ull a = A[4 * g + m];
        a = fma2(W0, E[m], a);
        a = fma2(W1, O[m], a);
        a = fma2(W2, E[m + 1], a);
        a = fma2(W3, O[m + 1], a);
        a = fma2(W4, E[m + 2], a);
        A[4 * g + m] = a;
      }
    }
  }

  __half* yp = g_y1 + (size_t)p * 4096;
  #pragma unroll
  for (int g = 0; g < 2; g++) {
    int h = hb + 32 * g;
    unsigned hh[4];
    #pragma unroll
    for (int m = 0; m < 4; m++) {
      float a0, a1; upk(a0, a1, A[4 * g + m]);
      __half2 p2 = __floats2half2_rn(silu_f(a0), silu_f(a1));
      hh[m] = *reinterpret_cast<unsigned*>(&p2);
    }
    *reinterpret_cast<uint4*>(yp + h * 64 + 8 * wq) =
        make_uint4(hh[0], hh[1], hh[2], hh[3]);
  }
}

// ---------------- kernel 2: pointwise + attn + top-38 + output ------------
// (byte-identical to R8: fp16-packed bitonic sort, pruned merge cone)
__global__ void __launch_bounds__(256, 3)
k_attn(const float* __restrict__ x, float* __restrict__ out) {
  extern __shared__ float park[];           // 64*256 floats = 64KB
  int tid = threadIdx.x;
  int t = blockIdx.x * 256 + tid;
  int b = t >> 16;
  int sp = t & 65535;
  size_t xb = (size_t)b * 4194304 + (size_t)sp;   // + c*65536

  ull h2[4] = {c2.b1o[0], c2.b1o[1], c2.b1o[2], c2.b1o[3]};
  #pragma unroll
  for (int c = 0; c < 64; c++) {
    float xv = __ldg(x + xb + (size_t)c * 65536);
    ull xx = pk(xv, xv);
    #pragma unroll
    for (int j = 0; j < 4; j++) h2[j] = fma2(c2.w1o[c * 4 + j], xx, h2[j]);
  }
  ull hb2[4];
  #pragma unroll
  for (int j = 0; j < 4; j++) {
    float u, v; upk(u, v, h2[j]);
    hb2[j] = pk(silu_f(u), silu_f(v));
  }

  __half2 ph[32];
  float* mypark = park + tid;
  #pragma unroll
  for (int i = 0; i < 32; i++) {
    ull accA = pk(c2.b2[i], 0.0f);
    ull accB = pk(c2.b2[i + 32], 0.0f);
    #pragma unroll
    for (int j = 0; j < 4; j++) {
      accA = fma2(c2.w2o[i * 4 + j], hb2[j], accA);
      accB = fma2(c2.w2o[(i + 32) * 4 + j], hb2[j], accB);
    }
    float loA, hiA, loB, hiB;
    upk(loA, hiA, accA); upk(loB, hiB, accB);
    float y1A = __half2float(__ldg(g_y1 + xb + (size_t)i * 65536));
    float y1B = __half2float(__ldg(g_y1 + xb + (size_t)(i + 32) * 65536));
    float aA = y1A * (loA + hiA);
    float aB = y1B * (loB + hiB);
    mypark[i * 256] = aA;
    mypark[(i + 32) * 256] = aB;
    ph[i] = __floats2half2_rn(aA, -aB);
  }

  #pragma unroll
  for (int k = 2; k <= 32; k <<= 1) {
    #pragma unroll
    for (int j = k >> 1; j > 0; j >>= 1) {
      #pragma unroll
      for (int i = 0; i < 32; i++) {
        int l = i ^ j;
        if (l > i) {
          __half2 a = ph[i], bz = ph[l];
          __half2 mn = __hmin2(a, bz), mx = __hmax2(a, bz);
          if ((i & k) == 0) { ph[i] = mn; ph[l] = mx; }
          else              { ph[i] = mx; ph[l] = mn; }
        }
      }
    }
  }

  __half hv[32];
  #pragma unroll
  for (int i = 0; i < 32; i++) {
    __half2 sw = __lowhigh2highlow(ph[i]);
    __half2 m = __hmin2(ph[i], __hneg2(sw));
    hv[i] = __low2half(m);
  }
  #pragma unroll
  for (int i = 0; i < 16; i++) hv[i + 16] = __hmax(hv[i], hv[i + 16]);
  #pragma unroll
  for (int i = 16; i < 24; i++) hv[i + 8] = __hmax(hv[i], hv[i + 8]);
  #pragma unroll
  for (int i = 24; i < 28; i++) hv[i] = __hmin(hv[i], hv[i + 4]);
  hv[26] = __hmax(hv[24], hv[26]);
  hv[27] = __hmax(hv[25], hv[27]);
  float thr = __half2float(__hmin(hv[26], hv[27]));
  float alpha = c2.alpha;

  #pragma unroll
  for (int c = 0; c < 64; c++) {
    float a  = mypark[c * 256];
    float xv = __ldg(x + xb + (size_t)c * 65536);
    float r  = (a >= thr) ? fmaf(alpha, a, xv) : xv;
    out[xb + (size_t)c * 65536] = r;
  }
}

// ---------------------------------------------------------------------------
extern "C" void kernel_launch(void* const* d_in, const int* in_sizes, int n_in,
                              void* d_out, int out_size) {
  const float* x    = (const float*)d_in[0];
  const float* wdw  = (const float*)d_in[1];
  const float* g1   = (const float*)d_in[2];
  const float* be1  = (const float*)d_in[3];
  const float* m1   = (const float*)d_in[4];
  const float* v1   = (const float*)d_in[5];
  const float* wp1  = (const float*)d_in[6];
  const float* bp1  = (const float*)d_in[7];
  const float* g2   = (const float*)d_in[8];
  const float* be2  = (const float*)d_in[9];
  const float* m2   = (const float*)d_in[10];
  const float* v2   = (const float*)d_in[11];
  const float* wp2  = (const float*)d_in[12];
  const float* bp2  = (const float*)d_in[13];
  const float* alpha= (const float*)d_in[14];
  float* out = (float*)d_out;

  k_dwconv<<<4096, 256>>>(x, wdw, g1, be1, m1, v1, wp1, bp1,
                          g2, be2, m2, v2, wp2, bp2, alpha);

  void* gaddr = nullptr;
  cudaGetSymbolAddress(&gaddr, g_c2);
  cudaMemcpyToSymbolAsync(c2, gaddr, sizeof(C2), 0,
                          cudaMemcpyDeviceToDevice, 0);

  cudaFuncSetAttribute(k_attn, cudaFuncAttributeMaxDynamicSharedMemorySize,
                       65536);
  k_attn<<<1024, 256, 65536>>>(x, out);
}

// round 10
// speedup vs baseline: 1.6320x; 1.0546x over previous
#include <cuda_runtime.h>
#include <cuda_fp16.h>

// B=4, C=64, D=16, H=64, W=64, C8=8, k=38 -> thr = rank-26 ascending of 64
#define EPSBN 1e-5f
typedef unsigned long long ull;

// ---------------- packed f32x2 helpers (fma pipe) ----------------
__device__ __forceinline__ ull pk(float lo, float hi) {
  ull r; asm("mov.b64 %0,{%1,%2};" : "=l"(r) : "f"(lo), "f"(hi)); return r;
}
__device__ __forceinline__ void upk(float& lo, float& hi, ull v) {
  asm("mov.b64 {%0,%1},%2;" : "=f"(lo), "=f"(hi) : "l"(v));
}
__device__ __forceinline__ ull fma2(ull a, ull b, ull c) {
  ull d; asm("fma.rn.f32x2 %0,%1,%2,%3;" : "=l"(d) : "l"(a), "l"(b), "l"(c)); return d;
}
__device__ __forceinline__ float silu_f(float v) {
  return v * (1.0f / (1.0f + __expf(-v)));
}

// ---------------- params ----------------
struct C2 {
  ull w1o[256];   // [c*4+j] = pk(w1t[c][2j], w1t[c][2j+1]), bn2 scale folded
  ull w2o[256];   // [c*4+j] = pk(w2[c][2j], w2[c][2j+1])
  ull b1o[4];     // pk(b1_eff[2j], b1_eff[2j+1])
  float b2[64];
  float alpha;
};
__device__   C2 g_c2;
__constant__ C2 c2;
__device__ __half g_y1[16777216];   // 32MB; linear indexing matches x

// ---------------- kernel 1: depthwise conv + BN + SiLU -> fp16 y1 ----------
// (R9 committed version: 8-wide tiles, 3 aligned LDS.128/row, conflict-free
// lane remap, pitch 76, f32x2 accumulation, smem packed weights)
#define PITCH 76
__global__ void __launch_bounds__(256)
k_dwconv(const float* __restrict__ x,
         const float* __restrict__ wdw,
         const float* __restrict__ g1, const float* __restrict__ be1,
         const float* __restrict__ m1, const float* __restrict__ v1,
         const float* __restrict__ wp1, const float* __restrict__ bp1,
         const float* __restrict__ g2, const float* __restrict__ be2,
         const float* __restrict__ m2, const float* __restrict__ v2,
         const float* __restrict__ wp2, const float* __restrict__ bp2,
         const float* __restrict__ alpha) {
  __shared__ float tile[68 * PITCH];
  __shared__ ull Wsm[25];
  int p = blockIdx.x;               // ((b*64+c)*16+d)
  int c = (p >> 4) & 63;
  int tid = threadIdx.x;

  if (p == 0) {
    int cc = tid >> 2, j = tid & 3;
    int o0 = 2 * j, o1 = o0 + 1;
    float s2a = __ldg(g2 + o0) * rsqrtf(__ldg(v2 + o0) + EPSBN);
    float s2b = __ldg(g2 + o1) * rsqrtf(__ldg(v2 + o1) + EPSBN);
    g_c2.w1o[cc * 4 + j] = pk(__ldg(wp1 + o0 * 64 + cc) * s2a,
                              __ldg(wp1 + o1 * 64 + cc) * s2b);
    g_c2.w2o[cc * 4 + j] = pk(__ldg(wp2 + cc * 8 + o0), __ldg(wp2 + cc * 8 + o1));
    if (tid < 4) {
      int p0 = 2 * tid, p1 = p0 + 1;
      float sa = __ldg(g2 + p0) * rsqrtf(__ldg(v2 + p0) + EPSBN);
      float sb = __ldg(g2 + p1) * rsqrtf(__ldg(v2 + p1) + EPSBN);
      g_c2.b1o[tid] = pk((__ldg(bp1 + p0) - __ldg(m2 + p0)) * sa + __ldg(be2 + p0),
                         (__ldg(bp1 + p1) - __ldg(m2 + p1)) * sb + __ldg(be2 + p1));
    }
    if (tid < 64) g_c2.b2[tid] = __ldg(bp2 + tid);
    if (tid == 0) g_c2.alpha = __ldg(alpha);
  }

  if (tid < 25) {
    float s1 = __ldg(g1 + c) * rsqrtf(__ldg(v1 + c) + EPSBN);
    float w = __ldg(wdw + c * 25 + tid) * s1;
    Wsm[tid] = pk(w, w);
  }

  for (int i = tid; i < 68 * PITCH; i += 256) tile[i] = 0.f;
  __syncthreads();
  const float* xp = x + (size_t)p * 4096;
  #pragma unroll
  for (int it = 0; it < 4; it++) {
    int i = tid + it * 256;
    int h = i >> 4, q = i & 15;
    float4 v = *reinterpret_cast<const float4*>(xp + h * 64 + q * 4);
    float* dst = &tile[(h + 2) * PITCH + q * 4 + 2];
    dst[0] = v.x; dst[1] = v.y; dst[2] = v.z; dst[3] = v.w;
  }
  __syncthreads();

  float t1;
  {
    float s1 = __ldg(g1 + c) * rsqrtf(__ldg(v1 + c) + EPSBN);
    t1 = __ldg(be1 + c) - __ldg(m1 + c) * s1;
  }

  int wq = (tid & 3) | ((tid >> 1) & 4);           // 0..7
  int hb = ((tid >> 2) & 1) | ((tid >> 3) & 0x1E); // 0..31; rows hb, hb+32

  ull A[8];
  #pragma unroll
  for (int m = 0; m < 8; m++) A[m] = pk(t1, t1);

  #pragma unroll
  for (int r = 0; r < 5; r++) {
    ull W0 = Wsm[5*r+0], W1 = Wsm[5*r+1], W2 = Wsm[5*r+2],
        W3 = Wsm[5*r+3], W4 = Wsm[5*r+4];
    #pragma unroll
    for (int g = 0; g < 2; g++) {
      const float* row = &tile[(hb + 32 * g + r) * PITCH + 8 * wq];
      float4 Q0 = *reinterpret_cast<const float4*>(row);
      float4 Q1 = *reinterpret_cast<const float4*>(row + 4);
      float4 Q2 = *reinterpret_cast<const float4*>(row + 8);
      ull E[6] = {pk(Q0.x, Q0.y), pk(Q0.z, Q0.w), pk(Q1.x, Q1.y),
                  pk(Q1.z, Q1.w), pk(Q2.x, Q2.y), pk(Q2.z, Q2.w)};
      ull O[5] = {pk(Q0.y, Q0.z), pk(Q0.w, Q1.x), pk(Q1.y, Q1.z),
                  pk(Q1.w, Q2.x), pk(Q2.y, Q2.z)};
      #pragma unroll
      for (int m = 0; m < 4; m++) {
        ull a = A[4 * g + m];
        a = fma2(W0, E[m], a);
        a = fma2(W1, O[m], a);
        a = fma2(W2, E[m + 1], a);
        a = fma2(W3, O[m + 1], a);
        a = fma2(W4, E[m + 2], a);
        A[4 * g + m] = a;
      }
    }
  }

  __half* yp = g_y1 + (size_t)p * 4096;
  #pragma unroll
  for (int g = 0; g < 2; g++) {
    int h = hb + 32 * g;
    unsigned hh[4];
    #pragma unroll
    for (int m = 0; m < 4; m++) {
      float a0, a1; upk(a0, a1, A[4 * g + m]);
      __half2 p2 = __floats2half2_rn(silu_f(a0), silu_f(a1));
      hh[m] = *reinterpret_cast<unsigned*>(&p2);
    }
    *reinterpret_cast<uint4*>(yp + h * 64 + 8 * wq) =
        make_uint4(hh[0], hh[1], hh[2], hh[3]);
  }
}

// ---------------- kernel 2: pointwise + attn + top-38 + output ------------
// fp16 keys park in smem (32KB), 4 CTAs/SM. Sort keys = half2(aA, -aB);
// park stores the key itself; pass 3 unpacks (aB = -hi). Entire k=64 merge
// cone computed in packed half2 (16 ops).
__global__ void __launch_bounds__(256, 4)
k_attn(const float* __restrict__ x, float* __restrict__ out) {
  extern __shared__ __half2 park[];         // [32][256] keys = 32KB
  int tid = threadIdx.x;
  int t = blockIdx.x * 256 + tid;
  int b = t >> 16;
  int sp = t & 65535;
  size_t xb = (size_t)b * 4194304 + (size_t)sp;   // + c*65536

  // pass 1: 8 hidden pre-activations (packed over o-pairs)
  ull h2[4] = {c2.b1o[0], c2.b1o[1], c2.b1o[2], c2.b1o[3]};
  #pragma unroll
  for (int c = 0; c < 64; c++) {
    float xv = __ldg(x + xb + (size_t)c * 65536);
    ull xx = pk(xv, xv);
    #pragma unroll
    for (int j = 0; j < 4; j++) h2[j] = fma2(c2.w1o[c * 4 + j], xx, h2[j]);
  }
  ull hb2[4];
  #pragma unroll
  for (int j = 0; j < 4; j++) {
    float u, v; upk(u, v, h2[j]);
    hb2[j] = pk(silu_f(u), silu_f(v));
  }

  // pass 2: attn for c and c+32 -> fp16 key half2(aA, -aB); park + sort regs
  __half2 ph[32];
  __half2* mypark = park + tid;
  #pragma unroll
  for (int i = 0; i < 32; i++) {
    ull accA = pk(c2.b2[i], 0.0f);
    ull accB = pk(c2.b2[i + 32], 0.0f);
    #pragma unroll
    for (int j = 0; j < 4; j++) {
      accA = fma2(c2.w2o[i * 4 + j], hb2[j], accA);
      accB = fma2(c2.w2o[(i + 32) * 4 + j], hb2[j], accB);
    }
    float loA, hiA, loB, hiB;
    upk(loA, hiA, accA); upk(loB, hiB, accB);
    float y1A = __half2float(__ldg(g_y1 + xb + (size_t)i * 65536));
    float y1B = __half2float(__ldg(g_y1 + xb + (size_t)(i + 32) * 65536));
    __half2 key = __floats2half2_rn(y1A * (loA + hiA), -(y1B * (loB + hiB)));
    mypark[i * 256] = key;
    ph[i] = key;
  }

  // packed bitonic sort-32 (lo lane ascending real, hi lane ascending negated)
  #pragma unroll
  for (int k = 2; k <= 32; k <<= 1) {
    #pragma unroll
    for (int j = k >> 1; j > 0; j >>= 1) {
      #pragma unroll
      for (int i = 0; i < 32; i++) {
        int l = i ^ j;
        if (l > i) {
          __half2 a = ph[i], bz = ph[l];
          __half2 mn = __hmin2(a, bz), mx = __hmax2(a, bz);
          if ((i & k) == 0) { ph[i] = mn; ph[l] = mx; }
          else              { ph[i] = mx; ph[l] = mn; }
        }
      }
    }
  }

  // k=64 merge stage j=32 packed into HV[16]: HV[k]=(lower[2k], lower[2k+1])
  __half2 HV[16];
  #pragma unroll
  for (int k2 = 0; k2 < 16; k2++) {
    __half2 m0 = __hmin2(ph[2 * k2],
                         __hneg2(__lowhigh2highlow(ph[2 * k2])));
    __half2 m1 = __hmin2(ph[2 * k2 + 1],
                         __hneg2(__lowhigh2highlow(ph[2 * k2 + 1])));
    HV[k2] = __halves2half2(__low2half(m0), __low2half(m1));
  }
  // pruned cone to rank 26, fully packed (16 ops)
  #pragma unroll
  for (int i = 0; i < 8; i++) HV[i + 8] = __hmax2(HV[i], HV[i + 8]);
  #pragma unroll
  for (int i = 8; i < 12; i++) HV[i + 4] = __hmax2(HV[i], HV[i + 4]);
  HV[12] = __hmin2(HV[12], HV[14]);
  HV[13] = __hmin2(HV[13], HV[15]);
  HV[13] = __hmax2(HV[12], HV[13]);
  float thr = __half2float(__hmin(__low2half(HV[13]), __high2half(HV[13])));
  float alpha = c2.alpha;

  // pass 3: unpack parked keys (aA, -aB) + write out
  #pragma unroll
  for (int i = 0; i < 32; i++) {
    __half2 key = mypark[i * 256];
    float2 f = __half22float2(key);
    float aA = f.x, aB = -f.y;
    float xA = __ldg(x + xb + (size_t)i * 65536);
    float xB = __ldg(x + xb + (size_t)(i + 32) * 65536);
    float rA = (aA >= thr) ? fmaf(alpha, aA, xA) : xA;
    float rB = (aB >= thr) ? fmaf(alpha, aB, xB) : xB;
    out[xb + (size_t)i * 65536] = rA;
    out[xb + (size_t)(i + 32) * 65536] = rB;
  }
}

// ---------------------------------------------------------------------------
extern "C" void kernel_launch(void* const* d_in, const int* in_sizes, int n_in,
                              void* d_out, int out_size) {
  const float* x    = (const float*)d_in[0];
  const float* wdw  = (const float*)d_in[1];
  const float* g1   = (const float*)d_in[2];
  const float* be1  = (const float*)d_in[3];
  const float* m1   = (const float*)d_in[4];
  const float* v1   = (const float*)d_in[5];
  const float* wp1  = (const float*)d_in[6];
  const float* bp1  = (const float*)d_in[7];
  const float* g2   = (const float*)d_in[8];
  const float* be2  = (const float*)d_in[9];
  const float* m2   = (const float*)d_in[10];
  const float* v2   = (const float*)d_in[11];
  const float* wp2  = (const float*)d_in[12];
  const float* bp2  = (const float*)d_in[13];
  const float* alpha= (const float*)d_in[14];
  float* out = (float*)d_out;

  k_dwconv<<<4096, 256>>>(x, wdw, g1, be1, m1, v1, wp1, bp1,
                          g2, be2, m2, v2, wp2, bp2, alpha);

  void* gaddr = nullptr;
  cudaGetSymbolAddress(&gaddr, g_c2);
  cudaMemcpyToSymbolAsync(c2, gaddr, sizeof(C2), 0,
                          cudaMemcpyDeviceToDevice, 0);

  cudaFuncSetAttribute(k_attn, cudaFuncAttributeMaxDynamicSharedMemorySize,
                       32768);
  k_attn<<<1024, 256, 32768>>>(x, out);
}